// round 3
// baseline (speedup 1.0000x reference)
#include <cuda_runtime.h>
#include <cuda_fp16.h>

// ---------------------------------------------------------------------------
// HSLSTMRegressor: 3-layer LSTM (B=128, T=256, IN=64, H=512) + linear head + MSE.
// Persistent fp16-tensor-core kernel, weights resident in SMEM, custom global
// barrier between the 768 sequential (t,layer) cells. A-chunks double-buffered
// with register prefetch. Barrier spin is BOUNDED and traps on timeout so a
// deadlock shows up as a clean kernel error, never a container hang.
// ---------------------------------------------------------------------------

#define Bn   128
#define Tn   256
#define INn  64
#define Hn   512
#define NCTA 128
#define NTHR 256

// SMEM layout (bytes)
#define OFF_W0 0        // 32 x 584 halves  = 37376
#define OFF_W1 37376    // 32 x 1032 halves = 66048
#define OFF_W2 103424   // 32 x 1032 halves = 66048
#define OFF_A  169472   // 2 x 64 x 72 halves = 18432 (double buffer)
#define OFF_G  187904   // 64 x 32 floats   = 8192
#define OFF_C  196096   // 3 x 64 x 8 floats= 6144
#define OFF_B  202240   // 3 x 32 floats    = 384
#define SMEM_TOTAL 202624
#define ABUF_HALVES (64 * 72)

// ---------------- device scratch (static allocations only) -----------------
__device__ __align__(16) __half g_X[Tn * Bn * INn];      // x as [t][b][k], fp16
__device__ __align__(16) __half g_W0[2048 * 576];        // layer0 [Wih|Whh], gate-interleaved
__device__ __align__(16) __half g_W12[2 * 2048 * 1024];  // layers1,2 [Wih|Whh]
__device__ __align__(16) float  g_Bias[3 * 2048];        // b_ih + b_hh, gate-interleaved
__device__ __align__(16) __half g_Hbuf[3 * 2 * Bn * Hn]; // h per layer, ping-pong on t
__device__ unsigned int g_ctr[1024];                     // barrier counters, one per cell

// ---------------------------------------------------------------------------
__global__ void k_init() {
    int idx = blockIdx.x * blockDim.x + threadIdx.x;
    int n = 3 * 2 * Bn * Hn;
    for (int i = idx; i < n; i += gridDim.x * blockDim.x) g_Hbuf[i] = __float2half(0.f);
    if (idx < 1024) g_ctr[idx] = 0u;
}

__global__ void k_conv_x(const float* __restrict__ x) {
    int tot = Tn * Bn * INn;
    for (int i = blockIdx.x * blockDim.x + threadIdx.x; i < tot; i += gridDim.x * blockDim.x) {
        int t = i / (Bn * INn);
        int r = i - t * (Bn * INn);
        int b = r / INn;
        int k = r - b * INn;
        g_X[i] = __float2half(x[(size_t)b * Tn * INn + (size_t)t * INn + k]);
    }
}

// permuted row pr = 4*j + g  <->  source gate row g*512 + j (PyTorch i,f,g,o order)
__global__ void k_conv_w0(const float* __restrict__ wih, const float* __restrict__ whh) {
    int tot = 2048 * 576;
    for (int i = blockIdx.x * blockDim.x + threadIdx.x; i < tot; i += gridDim.x * blockDim.x) {
        int r = i / 576, k = i - r * 576;
        int j = r >> 2, g = r & 3;
        int src = g * 512 + j;
        float v = (k < 64) ? wih[src * 64 + k] : whh[(size_t)src * 512 + (k - 64)];
        g_W0[i] = __float2half(v);
    }
}

__global__ void k_conv_w12(const float* __restrict__ wih, const float* __restrict__ whh) {
    int tot = 2 * 2048 * 1024;
    for (int i = blockIdx.x * blockDim.x + threadIdx.x; i < tot; i += gridDim.x * blockDim.x) {
        int l = i >> 21;
        int rem = i & ((1 << 21) - 1);
        int r = rem >> 10, k = rem & 1023;
        int j = r >> 2, g = r & 3;
        int src = g * 512 + j;
        float v = (k < 512) ? wih[((size_t)l * 2048 + src) * 512 + k]
                            : whh[((size_t)l * 2048 + src) * 512 + (k - 512)];
        g_W12[i] = __float2half(v);
    }
}

__global__ void k_conv_b(const float* __restrict__ bih0, const float* __restrict__ bhh0,
                         const float* __restrict__ bihr, const float* __restrict__ bhhr) {
    int tot = 3 * 2048;
    for (int i = blockIdx.x * blockDim.x + threadIdx.x; i < tot; i += gridDim.x * blockDim.x) {
        int l = i / 2048, r = i - l * 2048;
        int j = r >> 2, g = r & 3;
        int src = g * 512 + j;
        float v = (l == 0) ? (bih0[src] + bhh0[src])
                           : (bihr[(l - 1) * 2048 + src] + bhhr[(l - 1) * 2048 + src]);
        g_Bias[i] = v;
    }
}

// ---------------------------------------------------------------------------
__device__ __forceinline__ void mma16816(float* c,
                                         unsigned a0, unsigned a1, unsigned a2, unsigned a3,
                                         unsigned b0, unsigned b1) {
    asm volatile(
        "mma.sync.aligned.m16n8k16.row.col.f32.f16.f16.f32 "
        "{%0,%1,%2,%3}, {%4,%5,%6,%7}, {%8,%9}, {%0,%1,%2,%3};\n"
        : "+f"(c[0]), "+f"(c[1]), "+f"(c[2]), "+f"(c[3])
        : "r"(a0), "r"(a1), "r"(a2), "r"(a3), "r"(b0), "r"(b1));
}

__device__ __forceinline__ float sigmoidf_(float x) { return 1.f / (1.f + __expf(-x)); }

__global__ void __launch_bounds__(NTHR, 1) k_lstm() {
    extern __shared__ __align__(16) unsigned char smraw[];
    __half* sW0 = (__half*)(smraw + OFF_W0);
    __half* sW1 = (__half*)(smraw + OFF_W1);
    __half* sW2 = (__half*)(smraw + OFF_W2);
    __half* sA  = (__half*)(smraw + OFF_A);
    float*  sG  = (float*)(smraw + OFF_G);
    float*  sC  = (float*)(smraw + OFF_C);
    float*  sB  = (float*)(smraw + OFF_B);

    const int tid   = threadIdx.x;
    const int cta   = blockIdx.x;
    const int mbase = (cta & 1) * 64;   // batch-row half
    const int cg    = cta >> 1;         // column group: h-cols [cg*8, cg*8+8)
    const int lane  = tid & 31;
    const int wid   = tid >> 5;
    const int mrow0 = (wid & 3) * 16;   // warp's 16 batch rows within the 64-slice
    const int ng0   = (wid >> 2) * 16;  // warp's 16 gate rows within the 32-slice
    const int lg    = lane >> 2;
    const int lt2   = (lane & 3) * 2;

    // ---- load this CTA's weight slice (all 3 layers) into SMEM, once ----
    for (int i = tid; i < 32 * 72; i += NTHR) {              // layer0: 576 halves/row
        int r = i / 72, s = i - r * 72;
        *(uint4*)(sW0 + r * 584 + s * 8) =
            *(const uint4*)(g_W0 + ((size_t)(cg * 32 + r)) * 576 + s * 8);
    }
    for (int i = tid; i < 32 * 128; i += NTHR) {             // layers1,2: 1024 halves/row
        int r = i >> 7, s = i & 127;
        *(uint4*)(sW1 + r * 1032 + s * 8) =
            *(const uint4*)(g_W12 + ((size_t)(cg * 32 + r)) * 1024 + s * 8);
        *(uint4*)(sW2 + r * 1032 + s * 8) =
            *(const uint4*)(g_W12 + ((size_t)(2048 + cg * 32 + r)) * 1024 + s * 8);
    }
    for (int i = tid; i < 96; i += NTHR) {
        int l = i >> 5, r = i & 31;
        sB[i] = g_Bias[l * 2048 + cg * 32 + r];
    }
    for (int i = tid; i < 3 * 64 * 8; i += NTHR) sC[i] = 0.f;
    __syncthreads();

    const int arow = tid >> 2;          // A staging: 64 rows x 64 cols per chunk
    const int acs  = (tid & 3) << 4;

    for (int t = 0; t < Tn; ++t) {
        for (int l = 0; l < 3; ++l) {
            const __half* srcA;
            int strideA, KA;
            if (l == 0) { srcA = g_X + (size_t)t * Bn * INn; strideA = INn; KA = INn; }
            else        { srcA = g_Hbuf + ((size_t)((l - 1) * 2 + (t & 1))) * Bn * Hn;
                          strideA = Hn; KA = Hn; }
            const __half* srcB = g_Hbuf + ((size_t)(l * 2 + ((t & 1) ^ 1))) * Bn * Hn;
            const __half* wbase = (l == 0) ? sW0 : ((l == 1) ? sW1 : sW2);
            const int wstr = (l == 0) ? 584 : 1032;
            const int nch = (KA + Hn) >> 6;     // 9 (layer0) or 16 chunks of K=64

            float acc0[4] = {0.f, 0.f, 0.f, 0.f};
            float acc1[4] = {0.f, 0.f, 0.f, 0.f};

            // prologue: prefetch chunk 0 into registers
            uint4 v0, v1;
            {
                const __half* p = srcA + (size_t)(mbase + arow) * strideA + acs;
                v0 = __ldcg((const uint4*)p);
                v1 = __ldcg((const uint4*)(p + 8));
            }

            for (int ch = 0; ch < nch; ++ch) {
                __half* abuf = sA + (ch & 1) * ABUF_HALVES;
                *(uint4*)(abuf + arow * 72 + acs)     = v0;
                *(uint4*)(abuf + arow * 72 + acs + 8) = v1;
                __syncthreads();

                // prefetch next chunk while MMAs run on this one
                if (ch + 1 < nch) {
                    int kb = (ch + 1) << 6;
                    const __half* p;
                    if (kb < KA) p = srcA + (size_t)(mbase + arow) * strideA + (kb + acs);
                    else         p = srcB + (size_t)(mbase + arow) * Hn + (kb - KA + acs);
                    v0 = __ldcg((const uint4*)p);
                    v1 = __ldcg((const uint4*)(p + 8));
                }

                const int kb = ch << 6;
#pragma unroll
                for (int kk = 0; kk < 64; kk += 16) {
                    unsigned a0 = *(const unsigned*)(abuf + (mrow0 + lg)     * 72 + kk + lt2);
                    unsigned a1 = *(const unsigned*)(abuf + (mrow0 + lg + 8) * 72 + kk + lt2);
                    unsigned a2 = *(const unsigned*)(abuf + (mrow0 + lg)     * 72 + kk + lt2 + 8);
                    unsigned a3 = *(const unsigned*)(abuf + (mrow0 + lg + 8) * 72 + kk + lt2 + 8);
                    {
                        const __half* wp = wbase + (ng0 + lg) * wstr + kb + kk + lt2;
                        unsigned b0 = *(const unsigned*)wp;
                        unsigned b1 = *(const unsigned*)(wp + 8);
                        mma16816(acc0, a0, a1, a2, a3, b0, b1);
                    }
                    {
                        const __half* wp = wbase + (ng0 + 8 + lg) * wstr + kb + kk + lt2;
                        unsigned b0 = *(const unsigned*)wp;
                        unsigned b1 = *(const unsigned*)(wp + 8);
                        mma16816(acc1, a0, a1, a2, a3, b0, b1);
                    }
                }
            }
            __syncthreads();   // last MMA reads done before sG (and next-cell sA) writes

            // ---- dump gate pre-activations to SMEM ----
            {
                int m0 = mrow0 + lg;
                int nc = ng0 + lt2;
                sG[m0 * 32 + nc]           = acc0[0];
                sG[m0 * 32 + nc + 1]       = acc0[1];
                sG[(m0 + 8) * 32 + nc]     = acc0[2];
                sG[(m0 + 8) * 32 + nc + 1] = acc0[3];
                sG[m0 * 32 + nc + 8]       = acc1[0];
                sG[m0 * 32 + nc + 9]       = acc1[1];
                sG[(m0 + 8) * 32 + nc + 8] = acc1[2];
                sG[(m0 + 8) * 32 + nc + 9] = acc1[3];
            }
            __syncthreads();

            // ---- elementwise LSTM cell for the CTA's 64x8 (batch, h-col) tile ----
            __half* hdst = g_Hbuf + ((size_t)(l * 2 + (t & 1))) * Bn * Hn;
            for (int idx = tid; idx < 512; idx += NTHR) {
                int m = idx >> 3, j = idx & 7;
                float gi = sG[m * 32 + 4 * j + 0] + sB[l * 32 + 4 * j + 0];
                float gf = sG[m * 32 + 4 * j + 1] + sB[l * 32 + 4 * j + 1];
                float gg = sG[m * 32 + 4 * j + 2] + sB[l * 32 + 4 * j + 2];
                float go = sG[m * 32 + 4 * j + 3] + sB[l * 32 + 4 * j + 3];
                float cp = sC[(l * 64 + m) * 8 + j];
                float cn = sigmoidf_(gf) * cp + sigmoidf_(gi) * tanhf(gg);
                float hn = sigmoidf_(go) * tanhf(cn);
                sC[(l * 64 + m) * 8 + j] = cn;
                hdst[(size_t)(mbase + m) * Hn + cg * 8 + j] = __float2half(hn);
            }
            __threadfence();

            // ---- global barrier for this cell (bounded spin; traps on timeout) ----
            {
                int s = t * 3 + l;
                __syncthreads();
                if (tid == 0) {
                    unsigned arrived = atomicAdd(&g_ctr[s], 1u) + 1u;
                    if (arrived < (unsigned)gridDim.x) {
                        volatile unsigned* pc = &g_ctr[s];
                        long long spins = 0;
                        while (*pc < (unsigned)gridDim.x) {
                            __nanosleep(64);
                            if (++spins > (1LL << 28)) __trap();   // fail loud, not hang
                        }
                    }
                    __threadfence();   // order peer-h reads after counter observation
                }
                __syncthreads();
            }
        }
    }
}

// ---------------------------------------------------------------------------
__global__ void k_out(const float* __restrict__ wout, const float* __restrict__ bout,
                      const float* __restrict__ y, float* __restrict__ out, int out_size) {
    __shared__ float sred[128];
    int b = threadIdx.x;
    const __half* h = g_Hbuf + ((size_t)(2 * 2 + ((Tn - 1) & 1))) * Bn * Hn + (size_t)b * Hn;
    float s = 0.f;
    for (int j = 0; j < Hn; ++j) s += __half2float(h[j]) * wout[j];
    s += bout[0];
    float d = s - y[b];
    sred[b] = d * d;
    __syncthreads();
    for (int st = 64; st > 0; st >>= 1) {
        if (b < st) sred[b] += sred[b + st];
        __syncthreads();
    }
    float loss = sred[0] * (1.f / 128.f);
    if (out_size == 1) {
        if (b == 0) out[0] = loss;
    } else {
        if (b < out_size) out[b] = s;
        if (b == 0 && out_size > Bn) out[Bn] = loss;
    }
}

// ---------------------------------------------------------------------------
extern "C" void kernel_launch(void* const* d_in, const int* in_sizes, int n_in,
                              void* d_out, int out_size) {
    const float* x    = (const float*)d_in[0];
    const float* y    = (const float*)d_in[1];
    const float* wih0 = (const float*)d_in[2];
    const float* whh0 = (const float*)d_in[3];
    const float* bih0 = (const float*)d_in[4];
    const float* bhh0 = (const float*)d_in[5];
    const float* wihr = (const float*)d_in[6];
    const float* whhr = (const float*)d_in[7];
    const float* bihr = (const float*)d_in[8];
    const float* bhhr = (const float*)d_in[9];
    const float* wout = (const float*)d_in[10];
    const float* bout = (const float*)d_in[11];

    cudaFuncSetAttribute(k_lstm, cudaFuncAttributeMaxDynamicSharedMemorySize, SMEM_TOTAL);

    k_init<<<512, 256>>>();
    k_conv_x<<<512, 256>>>(x);
    k_conv_w0<<<512, 256>>>(wih0, whh0);
    k_conv_w12<<<1024, 256>>>(wihr, whhr);
    k_conv_b<<<24, 256>>>(bih0, bhh0, bihr, bhhr);
    k_lstm<<<NCTA, NTHR, SMEM_TOTAL>>>();
    k_out<<<1, 128>>>(wout, bout, y, (float*)d_out, out_size);
}